// round 1
// baseline (speedup 1.0000x reference)
#include <cuda_runtime.h>
#include <math.h>

// ---------------- problem constants ----------------
#define TT   5
#define HH   60
#define WWID 108
#define CDIM 512
#define NTOK (TT*HH*WWID)        // 32400
#define QS   (NTOK*CDIM)         // 16588800
#define PTOK (TT*144)            // 720
#define PS   (PTOK*CDIM)         // 368640
#define NWIN 144
#define NKEY 1050                // 225 window + 600 rolled + 225 pooled
#define WA   225
#define HEADS 4
#define HD    128
#define SCALE 0.08838834764831845f   // 128^-0.5

// ---------------- scratch (device globals; no runtime alloc) ----------------
__device__ float g_qkv   [3*QS];          // q/k/v planes for x   (~199 MB)
__device__ float g_qkvp  [3*PS];          // q/k/v planes for pooled
__device__ float g_kall  [NWIN*NKEY*CDIM];// gathered K (~310 MB)
__device__ float g_vall  [NWIN*NKEY*CDIM];// gathered V (~310 MB)
__device__ float g_attnout[QS];           // attention output (~66 MB)
__device__ int   g_valid_ind[120];

// ---------------- VALID_IND table (matches reference masks) ----------------
__global__ void init_valid_kernel() {
    int cnt = 0;
    for (int idx = 0; idx < 180; idx++) {
        int si = idx / 45, l = idx % 45, r = l / 9, c = l % 9;
        bool valid;
        if      (si == 0) valid = (r >= 3) || (c >= 5);   // tl
        else if (si == 1) valid = (r >= 3) || (c <  4);   // tr
        else if (si == 2) valid = (r <  2) || (c >= 5);   // bl
        else              valid = (r <  2) || (c <  4);   // br
        if (valid) g_valid_ind[cnt++] = idx;
    }
}

// ---------------- generic SGEMM: Out = A @ W^T + bias ----------------
// mode 0: A = g_attnout, Out = Outext (row-major M x N)          [proj]
// mode 1: A = Aext (x tokens), Out = g_qkv  split into 3 planes  [qkv x]
// mode 2: A = Aext (x_pooled, row remap), Out = g_qkvp split     [qkv pooled]
__global__ __launch_bounds__(256)
void gemm_kernel(const float* __restrict__ Aext, const float* __restrict__ W,
                 const float* __restrict__ bias, float* __restrict__ Outext,
                 int M, int N, int K, int mode)
{
    __shared__ float As[16][64];
    __shared__ float Bs[16][64];
    int tid = threadIdx.x;
    int tx = tid & 15, ty = tid >> 4;
    int m0 = blockIdx.y * 64, n0 = blockIdx.x * 64;

    const float* A = (mode == 0) ? g_attnout : Aext;

    float acc[4][4] = {};

    for (int k0 = 0; k0 < K; k0 += 16) {
        #pragma unroll
        for (int l = 0; l < 4; l++) {
            int idx = tid + l * 256;
            int rr = idx >> 4, kk = idx & 15;
            int m = m0 + rr;
            float av = 0.f;
            if (m < M) {
                int sr = (mode == 2) ? ((m % 144) * 5 + m / 144) : m;
                av = A[(size_t)sr * K + k0 + kk];
            }
            As[kk][rr] = av;
            Bs[kk][rr] = W[(size_t)(n0 + rr) * K + k0 + kk];
        }
        __syncthreads();
        #pragma unroll
        for (int kk = 0; kk < 16; kk++) {
            float4 a = ((const float4*)As[kk])[ty];
            float4 b = ((const float4*)Bs[kk])[tx];
            acc[0][0] += a.x*b.x; acc[0][1] += a.x*b.y; acc[0][2] += a.x*b.z; acc[0][3] += a.x*b.w;
            acc[1][0] += a.y*b.x; acc[1][1] += a.y*b.y; acc[1][2] += a.y*b.z; acc[1][3] += a.y*b.w;
            acc[2][0] += a.z*b.x; acc[2][1] += a.z*b.y; acc[2][2] += a.z*b.z; acc[2][3] += a.z*b.w;
            acc[3][0] += a.w*b.x; acc[3][1] += a.w*b.y; acc[3][2] += a.w*b.z; acc[3][3] += a.w*b.w;
        }
        __syncthreads();
    }

    #pragma unroll
    for (int i = 0; i < 4; i++) {
        int m = m0 + ty * 4 + i;
        if (m >= M) continue;
        #pragma unroll
        for (int j = 0; j < 4; j++) {
            int n = n0 + tx * 4 + j;
            float v = acc[i][j] + bias[n];
            if (mode == 0) {
                Outext[(size_t)m * N + n] = v;
            } else {
                float* base = (mode == 1) ? g_qkv : g_qkvp;
                int pstride  = (mode == 1) ? QS : PS;
                base[(size_t)(n >> 9) * pstride + (size_t)m * 512 + (n & 511)] = v;
            }
        }
    }
}

// ---------------- gather K_all / V_all per window ----------------
__global__ __launch_bounds__(128)
void gather_kv_kernel()
{
    int n = blockIdx.x;          // 0..1049
    int win = blockIdx.y;        // 0..143
    int wh = win / 12, ww = win % 12;
    int tid = threadIdx.x;       // 128 threads, one float4 each (512 floats)

    bool zero = false;
    const float* kbase = g_qkvp;   // dummy init
    const float* vbase = g_qkvp;
    int row = 0;

    if (n < WA) {
        // window tokens: n = t*45 + r*9 + c
        int t = n / 45, l = n % 45, r = l / 9, c = l % 9;
        row = (t * HH + wh * 5 + r) * WWID + ww * 9 + c;
        kbase = g_qkv + QS;  vbase = g_qkv + 2 * QS;
    } else if (n < 825) {
        // rolled: n-225 = t*120 + j ; j -> VALID_IND
        int j2 = n - 225, t = j2 / 120, j = j2 % 120;
        int vi = g_valid_ind[j];
        int si = vi / 45, l = vi % 45, r = l / 9, c = l % 9;
        // shifts = [(-2,-4),(-2,4),(2,-4),(2,4)]; rolled[i]=x[(i-s)%H]
        int dh = (si < 2) ?  2 : -2;
        int dw = ((si & 1) == 0) ? 4 : -4;
        int h = (wh * 5 + r + dh + HH) % HH;
        int w = (ww * 9 + c + dw + WWID) % WWID;
        row = (t * HH + h) * WWID + w;
        kbase = g_qkv + QS;  vbase = g_qkv + 2 * QS;
    } else {
        // pooled: n-825 = t*45 + fr*9 + fc ; patch center (wh,ww), pad (2,4)
        int j2 = n - 825, t = j2 / 45, p = j2 % 45, fr = p / 9, fc = p % 9;
        int gh = wh + fr - 2, gw = ww + fc - 4;
        if (gh < 0 || gh >= 12 || gw < 0 || gw >= 12) {
            zero = true;
        } else {
            row = t * 144 + gh * 12 + gw;
            kbase = g_qkvp + PS;  vbase = g_qkvp + 2 * PS;
        }
    }

    float4 kv = make_float4(0.f, 0.f, 0.f, 0.f);
    float4 vv = kv;
    if (!zero) {
        kv = ((const float4*)(kbase + (size_t)row * 512))[tid];
        vv = ((const float4*)(vbase + (size_t)row * 512))[tid];
    }
    size_t dst = ((size_t)win * NKEY + n) * 512;
    ((float4*)(g_kall + dst))[tid] = kv;
    ((float4*)(g_vall + dst))[tid] = vv;
}

// ---------------- flash attention (fp32) ----------------
// block = (qtile of 16, head, window). 128 threads = 16 queries x 8 dim-groups.
#define TQ 16
#define TK 32
__global__ __launch_bounds__(128)
void attn_kernel()
{
    int qt   = blockIdx.x;
    int head = blockIdx.y;
    int win  = blockIdx.z;
    int wh = win / 12, ww = win % 12;

    __shared__ float Ks[TK][HD];
    __shared__ float Vs[TK][HD];

    int tid = threadIdx.x;
    int q  = tid >> 3;          // 0..15
    int dg = tid & 7;           // 0..7
    int d0 = dg * 16;
    int qi = qt * TQ + q;

    // load Q into registers, pre-scaled
    float qreg[16];
    #pragma unroll
    for (int dd = 0; dd < 16; dd++) qreg[dd] = 0.f;
    if (qi < WA) {
        int t = qi / 45, l = qi % 45, r = l / 9, c = l % 9;
        int row = (t * HH + wh * 5 + r) * WWID + ww * 9 + c;
        const float* src = g_qkv + (size_t)row * 512 + head * HD + d0;
        #pragma unroll
        for (int dd = 0; dd < 16; dd++) qreg[dd] = src[dd] * SCALE;
    }

    float o[16];
    #pragma unroll
    for (int dd = 0; dd < 16; dd++) o[dd] = 0.f;
    float m_run = -1e30f, l_run = 0.f;

    for (int n0 = 0; n0 < NKEY; n0 += TK) {
        __syncthreads();
        // load K/V chunk: 32 keys x 128 floats = 1024 float4s; 8 per thread
        #pragma unroll
        for (int it = 0; it < 8; it++) {
            int idx = tid + it * 128;
            int k  = idx >> 5;      // 0..31
            int d4 = idx & 31;      // float4 idx within 128 floats
            int n = n0 + k;
            float4 kv = make_float4(0.f, 0.f, 0.f, 0.f), vv = kv;
            if (n < NKEY) {
                size_t base = ((size_t)win * NKEY + n) * 512 + head * HD;
                kv = ((const float4*)(g_kall + base))[d4];
                vv = ((const float4*)(g_vall + base))[d4];
            }
            ((float4*)Ks[k])[d4] = kv;
            ((float4*)Vs[k])[d4] = vv;
        }
        __syncthreads();

        float s[TK];
        #pragma unroll
        for (int k = 0; k < TK; k++) {
            float p = 0.f;
            const float4* kr = (const float4*)(Ks[k] + d0);
            #pragma unroll
            for (int d4 = 0; d4 < 4; d4++) {
                float4 kv = kr[d4];
                p += qreg[d4*4+0]*kv.x + qreg[d4*4+1]*kv.y
                   + qreg[d4*4+2]*kv.z + qreg[d4*4+3]*kv.w;
            }
            // reduce across the 8 dim-group lanes (aligned 8-lane groups)
            p += __shfl_xor_sync(0xffffffffu, p, 1);
            p += __shfl_xor_sync(0xffffffffu, p, 2);
            p += __shfl_xor_sync(0xffffffffu, p, 4);

            int n = n0 + k;
            if (n >= NKEY) {
                p = -1e30f;
            } else if (n >= 825) {
                int p2 = (n - 825) % 45;
                int fr = p2 / 9, fc = p2 % 9;
                int gh = wh + fr - 2, gw = ww + fc - 4;
                if (gh < 0 || gh >= 12 || gw < 0 || gw >= 12) p -= 100.f;
            }
            s[k] = p;
        }

        float cmax = -1e30f;
        #pragma unroll
        for (int k = 0; k < TK; k++) cmax = fmaxf(cmax, s[k]);
        float m_new = fmaxf(m_run, cmax);
        float alpha = __expf(m_run - m_new);
        l_run *= alpha;
        #pragma unroll
        for (int dd = 0; dd < 16; dd++) o[dd] *= alpha;

        #pragma unroll
        for (int k = 0; k < TK; k++) {
            float p = __expf(s[k] - m_new);
            l_run += p;
            const float4* vr = (const float4*)(Vs[k] + d0);
            #pragma unroll
            for (int d4 = 0; d4 < 4; d4++) {
                float4 vv = vr[d4];
                o[d4*4+0] += p * vv.x;
                o[d4*4+1] += p * vv.y;
                o[d4*4+2] += p * vv.z;
                o[d4*4+3] += p * vv.w;
            }
        }
        m_run = m_new;
    }

    if (qi < WA) {
        float inv = 1.f / l_run;
        float* dst = g_attnout + ((size_t)win * WA + qi) * 512 + head * HD + d0;
        #pragma unroll
        for (int dd = 0; dd < 16; dd++) dst[dd] = o[dd] * inv;
    }
}

// ---------------- launch ----------------
extern "C" void kernel_launch(void* const* d_in, const int* in_sizes, int n_in,
                              void* d_out, int out_size)
{
    const float* x        = (const float*)d_in[0]; // (1,5,60,108,512)
    const float* x_pooled = (const float*)d_in[1]; // (1,12,12,5,512)
    const float* qkv_w    = (const float*)d_in[2]; // (1536,512)
    const float* qkv_b    = (const float*)d_in[3]; // (1536,)
    const float* proj_w   = (const float*)d_in[4]; // (512,512)
    const float* proj_b   = (const float*)d_in[5]; // (512,)
    float* out = (float*)d_out;                    // (32400,512)

    init_valid_kernel<<<1, 1>>>();

    // QKV for x: M=32400, N=1536, K=512
    gemm_kernel<<<dim3(1536/64, (NTOK + 63)/64), 256>>>(
        x, qkv_w, qkv_b, nullptr, NTOK, 1536, 512, 1);

    // QKV for pooled: M=720, N=1536, K=512 (row remap inside)
    gemm_kernel<<<dim3(1536/64, (PTOK + 63)/64), 256>>>(
        x_pooled, qkv_w, qkv_b, nullptr, PTOK, 1536, 512, 2);

    // gather K_all / V_all
    gather_kv_kernel<<<dim3(NKEY, NWIN), 128>>>();

    // attention
    attn_kernel<<<dim3((WA + TQ - 1)/TQ, HEADS, NWIN), 128>>>();

    // projection: M=32400, N=512, K=512
    gemm_kernel<<<dim3(512/64, (NTOK + 63)/64), 256>>>(
        nullptr, proj_w, proj_b, out, NTOK, 512, 512, 0);
}

// round 3
// speedup vs baseline: 17.0775x; 17.0775x over previous
#include <cuda_runtime.h>
#include <cuda_fp16.h>
#include <stdint.h>
#include <math.h>

// ---------------- problem constants ----------------
#define TT    5
#define HH    60
#define WWID  108
#define CDIM  512
#define NTOK  (TT*HH*WWID)          // 32400
#define QS    (NTOK*CDIM)           // 16588800
#define PTOK  720
#define NWIN  144
#define NKEY  1050
#define NKP   1056                  // padded keys
#define WA    225
#define NB    (NWIN*4)              // 576 (win,head) batches
#define SCALE 0.08838834764831845f

// ---------------- scratch (device globals, f16-heavy) ----------------
__device__ __align__(256) __half hx    [QS];
__device__ __align__(256) __half hxp   [PTOK*CDIM];
__device__ __align__(256) __half hwqkv [1536*512];
__device__ __align__(256) __half hwproj[512*512];
__device__ __align__(256) __half hq [QS];
__device__ __align__(256) __half hk [QS];
__device__ __align__(256) __half hv [QS];
__device__ __align__(256) __half hqp[PTOK*CDIM];
__device__ __align__(256) __half hkp[PTOK*CDIM];
__device__ __align__(256) __half hvp[PTOK*CDIM];
__device__ __align__(256) __half g_qwin [NWIN*WA*CDIM];
__device__ __align__(256) __half g_kall [NWIN*NKEY*CDIM];
__device__ __align__(256) __half g_vall [NWIN*NKEY*CDIM];
__device__ __align__(256) __half g_vallT[NWIN*CDIM*NKP];
__device__ __align__(256) float  g_S    [(size_t)NB*WA*NKP];
__device__ __align__(256) __half g_P    [(size_t)NB*WA*NKP];
__device__ __align__(256) __half g_attn [QS];
__device__ int g_valid_ind[120];

// ---------------- helpers ----------------
__device__ __forceinline__ uint32_t smem_u32(const void* p) {
    uint32_t a;
    asm("{ .reg .u64 t; cvta.to.shared.u64 t, %1; cvt.u32.u64 %0, t; }" : "=r"(a) : "l"(p));
    return a;
}
__device__ __forceinline__ uint32_t h2u(__half2 h) { return *reinterpret_cast<uint32_t*>(&h); }

#define LDSM4(r0,r1,r2,r3,addr) \
    asm volatile("ldmatrix.sync.aligned.m8n8.x4.shared.b16 {%0,%1,%2,%3}, [%4];" \
        : "=r"(r0),"=r"(r1),"=r"(r2),"=r"(r3) : "r"(addr))

#define MMA16816(d,a,b) \
    asm volatile("mma.sync.aligned.m16n8k16.row.col.f32.f16.f16.f32 " \
        "{%0,%1,%2,%3}, {%4,%5,%6,%7}, {%8,%9}, {%0,%1,%2,%3};" \
        : "+f"((d)[0]),"+f"((d)[1]),"+f"((d)[2]),"+f"((d)[3]) \
        : "r"((a)[0]),"r"((a)[1]),"r"((a)[2]),"r"((a)[3]),"r"((b)[0]),"r"((b)[1]))

// ---------------- VALID_IND ----------------
__global__ void init_valid_kernel() {
    int cnt = 0;
    for (int idx = 0; idx < 180; idx++) {
        int si = idx / 45, l = idx % 45, r = l / 9, c = l % 9;
        bool valid;
        if      (si == 0) valid = (r >= 3) || (c >= 5);
        else if (si == 1) valid = (r >= 3) || (c <  4);
        else if (si == 2) valid = (r <  2) || (c >= 5);
        else              valid = (r <  2) || (c <  4);
        if (valid) g_valid_ind[cnt++] = idx;
    }
}

// ---------------- conversions ----------------
__global__ void f32_to_f16_kernel(const float* __restrict__ s, __half* __restrict__ d, int n4) {
    int i = blockIdx.x * blockDim.x + threadIdx.x;
    if (i < n4) {
        float4 f = ((const float4*)s)[i];
        ((uint2*)d)[i] = make_uint2(h2u(__floats2half2_rn(f.x, f.y)),
                                    h2u(__floats2half2_rn(f.z, f.w)));
    }
}
// pooled remap: hxp row m = x_pooled row (m%144)*5 + m/144
__global__ void conv_pooled_kernel(const float* __restrict__ xp) {
    int m = blockIdx.x;
    int sr = (m % 144) * 5 + m / 144;
    int tid = threadIdx.x; // 128
    float4 f = ((const float4*)(xp + (size_t)sr * 512))[tid];
    ((uint2*)(hxp + (size_t)m * 512))[tid] =
        make_uint2(h2u(__floats2half2_rn(f.x, f.y)), h2u(__floats2half2_rn(f.z, f.w)));
}

// ---------------- HMMA GEMM: Out = A @ B^T (+bias), 128x128 tile ----------------
// MODE 0: proj   A=g_attn B=hwproj M=32400 N=512  K=512  -> outF(+bias)
// MODE 1: qkv    A=hx     B=hwqkv  M=32400 N=1536 K=512  -> hq/hk/hv (+bias, q*SCALE)
// MODE 2: qkv-p  A=hxp    B=hwqkv  M=720   N=1536 K=512  -> hqp/hkp/hvp
// MODE 3: S      A=g_qwin B=g_kall M=225   N=1050 K=128  batched -> g_S fp32
// MODE 4: O      A=g_P    B=g_vallT M=225  N=128  K=1056 batched -> g_attn f16
template<int MODE>
__global__ __launch_bounds__(256)
void mma_gemm(float* __restrict__ outF, const float* __restrict__ bias)
{
    __shared__ __half As[128][40];
    __shared__ __half Bs[128][40];

    const int tid = threadIdx.x;
    const int z = blockIdx.z;
    const int win = z >> 2, head = z & 3;

    const __half* A; const __half* B;
    int M, N, K, lda, ldb;
    if (MODE == 0) { A = g_attn; B = hwproj; M = NTOK; N = 512;  K = 512;  lda = 512; ldb = 512; }
    if (MODE == 1) { A = hx;     B = hwqkv;  M = NTOK; N = 1536; K = 512;  lda = 512; ldb = 512; }
    if (MODE == 2) { A = hxp;    B = hwqkv;  M = PTOK; N = 1536; K = 512;  lda = 512; ldb = 512; }
    if (MODE == 3) { A = g_qwin + (size_t)win*WA*512 + head*128;
                     B = g_kall + (size_t)win*NKEY*512 + head*128;
                     M = WA; N = NKEY; K = 128; lda = 512; ldb = 512; }
    if (MODE == 4) { A = g_P    + (size_t)z*WA*NKP;
                     B = g_vallT + (size_t)win*512*NKP + (size_t)head*128*NKP;
                     M = WA; N = 128; K = NKP; lda = NKP; ldb = NKP; }

    const int m0 = blockIdx.y * 128;
    const int n0 = blockIdx.x * 128;
    const int lane = tid & 31, wid = tid >> 5;
    const int wm = wid & 3, wn = wid >> 2;

    float acc[2][8][4];
    #pragma unroll
    for (int a = 0; a < 2; a++)
        #pragma unroll
        for (int b = 0; b < 8; b++)
            #pragma unroll
            for (int c = 0; c < 4; c++) acc[a][b][c] = 0.f;

    for (int k0 = 0; k0 < K; k0 += 32) {
        __syncthreads();
        #pragma unroll
        for (int it = 0; it < 2; it++) {
            int idx = tid + it * 256;
            int r = idx >> 2, cq = idx & 3;
            int gc = k0 + cq * 8;
            uint4 va = make_uint4(0,0,0,0), vb = va;
            int gm = m0 + r;
            if (gm < M) va = *(const uint4*)(A + (size_t)gm * lda + gc);
            int gn = n0 + r;
            if (gn < N) vb = *(const uint4*)(B + (size_t)gn * ldb + gc);
            *(uint4*)&As[r][cq * 8] = va;
            *(uint4*)&Bs[r][cq * 8] = vb;
        }
        __syncthreads();
        #pragma unroll
        for (int ks = 0; ks < 2; ks++) {
            uint32_t afr[2][4];
            #pragma unroll
            for (int mi = 0; mi < 2; mi++) {
                uint32_t ad = smem_u32(&As[wm*32 + mi*16 + (lane & 15)][ks*16 + ((lane >> 4) << 3)]);
                LDSM4(afr[mi][0], afr[mi][1], afr[mi][2], afr[mi][3], ad);
            }
            uint32_t bfr[8][2];
            #pragma unroll
            for (int nj = 0; nj < 4; nj++) {
                uint32_t bd = smem_u32(&Bs[wn*64 + nj*16 + (lane & 15)][ks*16 + ((lane >> 4) << 3)]);
                uint32_t r0, r1, r2, r3;
                LDSM4(r0, r1, r2, r3, bd);
                bfr[nj*2][0] = r0;  bfr[nj*2][1] = r2;
                bfr[nj*2+1][0] = r1; bfr[nj*2+1][1] = r3;
            }
            #pragma unroll
            for (int mi = 0; mi < 2; mi++)
                #pragma unroll
                for (int ni = 0; ni < 8; ni++)
                    MMA16816(acc[mi][ni], afr[mi], bfr[ni]);
        }
    }

    // epilogue
    const int rr = lane >> 2, cc = (lane & 3) * 2;
    #pragma unroll
    for (int mi = 0; mi < 2; mi++) {
        #pragma unroll
        for (int ni = 0; ni < 8; ni++) {
            int col = n0 + wn * 64 + ni * 8 + cc;
            #pragma unroll
            for (int h = 0; h < 2; h++) {
                int row = m0 + wm * 32 + mi * 16 + rr + h * 8;
                if (row >= M) continue;
                float v0 = acc[mi][ni][h * 2 + 0];
                float v1 = acc[mi][ni][h * 2 + 1];
                if (MODE == 0) {
                    *(float2*)(outF + (size_t)row * 512 + col) =
                        make_float2(v0 + bias[col], v1 + bias[col + 1]);
                } else if (MODE == 1 || MODE == 2) {
                    v0 += bias[col]; v1 += bias[col + 1];
                    int pl = col >> 9, c2 = col & 511;
                    if (pl == 0) { v0 *= SCALE; v1 *= SCALE; }
                    __half* base;
                    if (MODE == 1) base = (pl == 0) ? hq : (pl == 1) ? hk : hv;
                    else           base = (pl == 0) ? hqp : (pl == 1) ? hkp : hvp;
                    *(uint32_t*)(base + (size_t)row * 512 + c2) = h2u(__floats2half2_rn(v0, v1));
                } else if (MODE == 3) {
                    if (col < NKEY)
                        *(float2*)(g_S + ((size_t)z * WA + row) * NKP + col) = make_float2(v0, v1);
                } else { // MODE 4
                    *(uint32_t*)(g_attn + (size_t)(win * WA + row) * 512 + head * 128 + col)
                        = h2u(__floats2half2_rn(v0, v1));
                }
            }
        }
    }
}

// ---------------- gathers (f16) ----------------
__global__ __launch_bounds__(64)
void gather_qwin_kernel() {
    int qq = blockIdx.x, win = blockIdx.y;
    int wh = win / 12, ww = win % 12;
    int t = qq / 45, l = qq % 45, r = l / 9, c = l % 9;
    int row = (t * HH + wh * 5 + r) * WWID + ww * 9 + c;
    ((uint4*)(g_qwin + (size_t)(win * WA + qq) * 512))[threadIdx.x] =
        ((const uint4*)(hq + (size_t)row * 512))[threadIdx.x];
}

__global__ __launch_bounds__(64)
void gather_kv_kernel() {
    int n = blockIdx.x, win = blockIdx.y;
    int wh = win / 12, ww = win % 12;
    int tid = threadIdx.x;

    bool zero = false;
    bool pooled = false;
    int row = 0;

    if (n < WA) {
        int t = n / 45, l = n % 45, r = l / 9, c = l % 9;
        row = (t * HH + wh * 5 + r) * WWID + ww * 9 + c;
    } else if (n < 825) {
        int j2 = n - 225, t = j2 / 120, j = j2 % 120;
        int vi = g_valid_ind[j];
        int si = vi / 45, l = vi % 45, r = l / 9, c = l % 9;
        int dh = (si < 2) ? 2 : -2;
        int dw = ((si & 1) == 0) ? 4 : -4;
        int h = (wh * 5 + r + dh + HH) % HH;
        int w = (ww * 9 + c + dw + WWID) % WWID;
        row = (t * HH + h) * WWID + w;
    } else {
        int j2 = n - 825, t = j2 / 45, p = j2 % 45, fr = p / 9, fc = p % 9;
        int gh = wh + fr - 2, gw = ww + fc - 4;
        if (gh < 0 || gh >= 12 || gw < 0 || gw >= 12) zero = true;
        else { row = t * 144 + gh * 12 + gw; pooled = true; }
    }

    uint4 kv = make_uint4(0,0,0,0), vv = kv;
    if (!zero) {
        const __half* kp = pooled ? hkp : hk;
        const __half* vp = pooled ? hvp : hv;
        kv = ((const uint4*)(kp + (size_t)row * 512))[tid];
        vv = ((const uint4*)(vp + (size_t)row * 512))[tid];
    }
    size_t dst = (size_t)(win * NKEY + n) * 512;
    ((uint4*)(g_kall + dst))[tid] = kv;
    ((uint4*)(g_vall + dst))[tid] = vv;
}

// V transpose per window: g_vall[win][n<1050][c] -> g_vallT[win][c][n], n-pad zero
__global__ __launch_bounds__(256)
void transpose_v_kernel() {
    __shared__ __half tile[32][33];
    int n0 = blockIdx.x * 32, c0 = blockIdx.y * 32, win = blockIdx.z;
    int tx = threadIdx.x, ty = threadIdx.y; // 32 x 8
    const __half* src = g_vall + (size_t)win * NKEY * 512;
    __half* dst = g_vallT + (size_t)win * 512 * NKP;
    #pragma unroll
    for (int i = 0; i < 4; i++) {
        int n = n0 + ty + i * 8;
        tile[ty + i * 8][tx] = (n < NKEY) ? src[(size_t)n * 512 + c0 + tx] : __float2half(0.f);
    }
    __syncthreads();
    #pragma unroll
    for (int i = 0; i < 4; i++) {
        int c = c0 + ty + i * 8;
        dst[(size_t)c * NKP + n0 + tx] = tile[tx][ty + i * 8];
    }
}

// ---------------- softmax: g_S fp32 (+bias) -> g_P f16 ----------------
__global__ __launch_bounds__(128)
void softmax_kernel() {
    int q = blockIdx.x, z = blockIdx.y;
    int win = z >> 2;
    int wh = win / 12, ww = win % 12;
    const float* srow = g_S + ((size_t)z * WA + q) * NKP;
    __half* prow = g_P + ((size_t)z * WA + q) * NKP;
    int tid = threadIdx.x, lane = tid & 31, wrp = tid >> 5;
    __shared__ float redm[4], reds[4];

    float v[9];
    float mx = -1e30f;
    #pragma unroll
    for (int i = 0; i < 9; i++) {
        int n = tid + i * 128;
        float s = -1e30f;
        if (n < NKEY) {
            s = srow[n];
            if (n >= 825) {
                int p2 = (n - 825) % 45;
                int fr = p2 / 9, fc = p2 % 9;
                int gh = wh + fr - 2, gw = ww + fc - 4;
                if (gh < 0 || gh >= 12 || gw < 0 || gw >= 12) s -= 100.f;
            }
        }
        v[i] = s;
        mx = fmaxf(mx, s);
    }
    #pragma unroll
    for (int o = 16; o; o >>= 1) mx = fmaxf(mx, __shfl_xor_sync(0xffffffffu, mx, o));
    if (lane == 0) redm[wrp] = mx;
    __syncthreads();
    mx = fmaxf(fmaxf(redm[0], redm[1]), fmaxf(redm[2], redm[3]));

    float sum = 0.f;
    #pragma unroll
    for (int i = 0; i < 9; i++) {
        int n = tid + i * 128;
        if (n < NKEY) { v[i] = __expf(v[i] - mx); sum += v[i]; }
        else v[i] = 0.f;
    }
    #pragma unroll
    for (int o = 16; o; o >>= 1) sum += __shfl_xor_sync(0xffffffffu, sum, o);
    if (lane == 0) reds[wrp] = sum;
    __syncthreads();
    sum = reds[0] + reds[1] + reds[2] + reds[3];
    float inv = 1.f / sum;
    #pragma unroll
    for (int i = 0; i < 9; i++) {
        int n = tid + i * 128;
        if (n < NKP) prow[n] = __float2half_rn(v[i] * inv);
    }
}

// ---------------- launch ----------------
extern "C" void kernel_launch(void* const* d_in, const int* in_sizes, int n_in,
                              void* d_out, int out_size)
{
    const float* x        = (const float*)d_in[0];
    const float* x_pooled = (const float*)d_in[1];
    const float* qkv_w    = (const float*)d_in[2];
    const float* qkv_b    = (const float*)d_in[3];
    const float* proj_w   = (const float*)d_in[4];
    const float* proj_b   = (const float*)d_in[5];
    float* out = (float*)d_out;

    init_valid_kernel<<<1, 1>>>();

    // f16 conversions
    {
        __half* dhx;    cudaGetSymbolAddress((void**)&dhx,    hx);
        __half* dwq;    cudaGetSymbolAddress((void**)&dwq,    hwqkv);
        __half* dwp;    cudaGetSymbolAddress((void**)&dwp,    hwproj);
        f32_to_f16_kernel<<<(QS/4 + 255)/256, 256>>>(x, dhx, QS/4);
        f32_to_f16_kernel<<<(1536*512/4 + 255)/256, 256>>>(qkv_w, dwq, 1536*512/4);
        f32_to_f16_kernel<<<(512*512/4 + 255)/256, 256>>>(proj_w, dwp, 512*512/4);
        conv_pooled_kernel<<<PTOK, 128>>>(x_pooled);
    }

    // QKV GEMMs
    mma_gemm<1><<<dim3(12, 254, 1), 256>>>(nullptr, qkv_b);
    mma_gemm<2><<<dim3(12, 6, 1),   256>>>(nullptr, qkv_b);

    // gathers
    gather_qwin_kernel<<<dim3(WA, NWIN), 64>>>();
    gather_kv_kernel<<<dim3(NKEY, NWIN), 64>>>();
    transpose_v_kernel<<<dim3(33, 16, NWIN), dim3(32, 8)>>>();

    // S = Q K^T  (batched)
    mma_gemm<3><<<dim3(9, 2, NB), 256>>>(nullptr, nullptr);

    // softmax -> P
    softmax_kernel<<<dim3(WA, NB), 128>>>();

    // O = P V
    mma_gemm<4><<<dim3(1, 2, NB), 256>>>(nullptr, nullptr);

    // proj
    mma_gemm<0><<<dim3(4, 254, 1), 256>>>(out, proj_b);
}

// round 5
// speedup vs baseline: 21.0801x; 1.2344x over previous
#include <cuda_runtime.h>
#include <cuda_fp16.h>
#include <stdint.h>
#include <math.h>

// ---------------- problem constants ----------------
#define TT    5
#define HH    60
#define WWID  108
#define CDIM  512
#define NTOK  (TT*HH*WWID)          // 32400
#define QS    (NTOK*CDIM)
#define PTOK  720
#define NWIN  144
#define NKEY  1050
#define NKEY2 1088                  // padded keys (17 chunks of 64)
#define WA    225
#define SCALE 0.08838834764831845f

// ---------------- scratch ----------------
__device__ __align__(256) __half hx    [QS];
__device__ __align__(256) __half hxp   [PTOK*CDIM];
__device__ __align__(256) __half hwqkv [1536*512];
__device__ __align__(256) __half hwproj[512*512];
__device__ __align__(256) __half hq [QS];
__device__ __align__(256) __half hk [QS];
__device__ __align__(256) __half hv [QS];
__device__ __align__(256) __half hqp[PTOK*CDIM];
__device__ __align__(256) __half hkp[PTOK*CDIM];
__device__ __align__(256) __half hvp[PTOK*CDIM];
__device__ __align__(256) __half g_kall[(size_t)NWIN*NKEY2*CDIM];
__device__ __align__(256) __half g_vall[(size_t)NWIN*NKEY2*CDIM];
__device__ __align__(256) float  g_bias[NWIN*NKEY2];
__device__ __align__(256) __half g_attn[QS];
__device__ int g_valid_ind[120];

// ---------------- helpers ----------------
__device__ __forceinline__ uint32_t smem_u32(const void* p) {
    uint32_t a;
    asm("{ .reg .u64 t; cvta.to.shared.u64 t, %1; cvt.u32.u64 %0, t; }" : "=r"(a) : "l"(p));
    return a;
}
__device__ __forceinline__ uint32_t h2u(__half2 h) { return *reinterpret_cast<uint32_t*>(&h); }

#define LDSM4(r0,r1,r2,r3,addr) \
    asm volatile("ldmatrix.sync.aligned.m8n8.x4.shared.b16 {%0,%1,%2,%3}, [%4];" \
        : "=r"(r0),"=r"(r1),"=r"(r2),"=r"(r3) : "r"(addr))
#define LDSM4T(r0,r1,r2,r3,addr) \
    asm volatile("ldmatrix.sync.aligned.m8n8.x4.trans.shared.b16 {%0,%1,%2,%3}, [%4];" \
        : "=r"(r0),"=r"(r1),"=r"(r2),"=r"(r3) : "r"(addr))

#define MMA16816(d,a,b0,b1) \
    asm volatile("mma.sync.aligned.m16n8k16.row.col.f32.f16.f16.f32 " \
        "{%0,%1,%2,%3}, {%4,%5,%6,%7}, {%8,%9}, {%0,%1,%2,%3};" \
        : "+f"((d)[0]),"+f"((d)[1]),"+f"((d)[2]),"+f"((d)[3]) \
        : "r"((a)[0]),"r"((a)[1]),"r"((a)[2]),"r"((a)[3]),"r"(b0),"r"(b1))

// ---------------- VALID_IND ----------------
__global__ void init_valid_kernel() {
    int cnt = 0;
    for (int idx = 0; idx < 180; idx++) {
        int si = idx / 45, l = idx % 45, r = l / 9, c = l % 9;
        bool valid;
        if      (si == 0) valid = (r >= 3) || (c >= 5);
        else if (si == 1) valid = (r >= 3) || (c <  4);
        else if (si == 2) valid = (r <  2) || (c >= 5);
        else              valid = (r <  2) || (c <  4);
        if (valid) g_valid_ind[cnt++] = idx;
    }
}

// ---------------- bias table: g_bias[win][n] ----------------
__global__ void bias_table_kernel() {
    int n = blockIdx.x * 64 + threadIdx.x;
    int win = blockIdx.y;
    if (n >= NKEY2) return;
    float b = 0.f;
    if (n >= NKEY) b = -1e30f;
    else if (n >= 825) {
        int p2 = (n - 825) % 45;
        int fr = p2 / 9, fc = p2 % 9;
        int gh = win / 12 + fr - 2, gw = win % 12 + fc - 4;
        if (gh < 0 || gh >= 12 || gw < 0 || gw >= 12) b = -100.f;
    }
    g_bias[win * NKEY2 + n] = b;
}

// ---------------- conversions ----------------
__global__ void f32_to_f16_kernel(const float* __restrict__ s, __half* __restrict__ d, int n4) {
    int i = blockIdx.x * blockDim.x + threadIdx.x;
    if (i < n4) {
        float4 f = ((const float4*)s)[i];
        ((uint2*)d)[i] = make_uint2(h2u(__floats2half2_rn(f.x, f.y)),
                                    h2u(__floats2half2_rn(f.z, f.w)));
    }
}
__global__ void conv_pooled_kernel(const float* __restrict__ xp) {
    int m = blockIdx.x;
    int sr = (m % 144) * 5 + m / 144;
    int tid = threadIdx.x;
    float4 f = ((const float4*)(xp + (size_t)sr * 512))[tid];
    ((uint2*)(hxp + (size_t)m * 512))[tid] =
        make_uint2(h2u(__floats2half2_rn(f.x, f.y)), h2u(__floats2half2_rn(f.z, f.w)));
}

// ---------------- HMMA GEMM: Out = A @ B^T (+bias) ----------------
template<int MODE>
__global__ __launch_bounds__(256)
void mma_gemm(float* __restrict__ outF, const float* __restrict__ bias)
{
    __shared__ __half As[128][40];
    __shared__ __half Bs[128][40];

    const int tid = threadIdx.x;
    const __half* A; const __half* B;
    int M, N;
    if (MODE == 0) { A = g_attn; B = hwproj; M = NTOK; N = 512;  }
    if (MODE == 1) { A = hx;     B = hwqkv;  M = NTOK; N = 1536; }
    if (MODE == 2) { A = hxp;    B = hwqkv;  M = PTOK; N = 1536; }
    const int K = 512, lda = 512, ldb = 512;

    const int m0 = blockIdx.y * 128;
    const int n0 = blockIdx.x * 128;
    const int lane = tid & 31, wid = tid >> 5;
    const int wm = wid & 3, wn = wid >> 2;

    float acc[2][8][4];
    #pragma unroll
    for (int a = 0; a < 2; a++)
        #pragma unroll
        for (int b = 0; b < 8; b++)
            #pragma unroll
            for (int c = 0; c < 4; c++) acc[a][b][c] = 0.f;

    for (int k0 = 0; k0 < K; k0 += 32) {
        __syncthreads();
        #pragma unroll
        for (int it = 0; it < 2; it++) {
            int idx = tid + it * 256;
            int r = idx >> 2, cq = idx & 3;
            int gc = k0 + cq * 8;
            uint4 va = make_uint4(0,0,0,0), vb = va;
            int gm = m0 + r;
            if (gm < M) va = *(const uint4*)(A + (size_t)gm * lda + gc);
            int gn = n0 + r;
            if (gn < N) vb = *(const uint4*)(B + (size_t)gn * ldb + gc);
            *(uint4*)&As[r][cq * 8] = va;
            *(uint4*)&Bs[r][cq * 8] = vb;
        }
        __syncthreads();
        #pragma unroll
        for (int ks = 0; ks < 2; ks++) {
            uint32_t afr[2][4];
            #pragma unroll
            for (int mi = 0; mi < 2; mi++) {
                uint32_t ad = smem_u32(&As[wm*32 + mi*16 + (lane & 15)][ks*16 + ((lane >> 4) << 3)]);
                LDSM4(afr[mi][0], afr[mi][1], afr[mi][2], afr[mi][3], ad);
            }
            uint32_t bfr[8][2];
            #pragma unroll
            for (int nj = 0; nj < 4; nj++) {
                uint32_t bd = smem_u32(&Bs[wn*64 + nj*16 + (lane & 15)][ks*16 + ((lane >> 4) << 3)]);
                uint32_t r0, r1, r2, r3;
                LDSM4(r0, r1, r2, r3, bd);
                bfr[nj*2][0] = r0;  bfr[nj*2][1] = r2;
                bfr[nj*2+1][0] = r1; bfr[nj*2+1][1] = r3;
            }
            #pragma unroll
            for (int mi = 0; mi < 2; mi++)
                #pragma unroll
                for (int ni = 0; ni < 8; ni++)
                    MMA16816(acc[mi][ni], afr[mi], bfr[ni][0], bfr[ni][1]);
        }
    }

    const int rr = lane >> 2, cc = (lane & 3) * 2;
    #pragma unroll
    for (int mi = 0; mi < 2; mi++) {
        #pragma unroll
        for (int ni = 0; ni < 8; ni++) {
            int col = n0 + wn * 64 + ni * 8 + cc;
            #pragma unroll
            for (int h = 0; h < 2; h++) {
                int row = m0 + wm * 32 + mi * 16 + rr + h * 8;
                if (row >= M) continue;
                float v0 = acc[mi][ni][h * 2 + 0];
                float v1 = acc[mi][ni][h * 2 + 1];
                if (MODE == 0) {
                    *(float2*)(outF + (size_t)row * 512 + col) =
                        make_float2(v0 + bias[col], v1 + bias[col + 1]);
                } else {
                    v0 += bias[col]; v1 += bias[col + 1];
                    int pl = col >> 9, c2 = col & 511;
                    if (pl == 0) { v0 *= SCALE; v1 *= SCALE; }
                    __half* base;
                    if (MODE == 1) base = (pl == 0) ? hq : (pl == 1) ? hk : hv;
                    else           base = (pl == 0) ? hqp : (pl == 1) ? hkp : hvp;
                    *(uint32_t*)(base + (size_t)row * 512 + c2) = h2u(__floats2half2_rn(v0, v1));
                }
            }
        }
    }
}

// ---------------- gather K_all / V_all (padded to NKEY2, f16) ----------------
__global__ __launch_bounds__(64)
void gather_kv_kernel() {
    int n = blockIdx.x, win = blockIdx.y;
    int wh = win / 12, ww = win % 12;
    int tid = threadIdx.x;

    bool zero = false;
    bool pooled = false;
    int row = 0;

    if (n >= NKEY) {
        zero = true;
    } else if (n < WA) {
        int t = n / 45, l = n % 45, r = l / 9, c = l % 9;
        row = (t * HH + wh * 5 + r) * WWID + ww * 9 + c;
    } else if (n < 825) {
        int j2 = n - 225, t = j2 / 120, j = j2 % 120;
        int vi = g_valid_ind[j];
        int si = vi / 45, l = vi % 45, r = l / 9, c = l % 9;
        int dh = (si < 2) ? 2 : -2;
        int dw = ((si & 1) == 0) ? 4 : -4;
        int h = (wh * 5 + r + dh + HH) % HH;
        int w = (ww * 9 + c + dw + WWID) % WWID;
        row = (t * HH + h) * WWID + w;
    } else {
        int j2 = n - 825, t = j2 / 45, p = j2 % 45, fr = p / 9, fc = p % 9;
        int gh = wh + fr - 2, gw = ww + fc - 4;
        if (gh < 0 || gh >= 12 || gw < 0 || gw >= 12) zero = true;
        else { row = t * 144 + gh * 12 + gw; pooled = true; }
    }

    uint4 kv = make_uint4(0,0,0,0), vv = kv;
    if (!zero) {
        const __half* kp = pooled ? hkp : hk;
        const __half* vp = pooled ? hvp : hv;
        kv = ((const uint4*)(kp + (size_t)row * 512))[tid];
        vv = ((const uint4*)(vp + (size_t)row * 512))[tid];
    }
    size_t dst = ((size_t)win * NKEY2 + n) * 512;
    ((uint4*)(g_kall + dst))[tid] = kv;
    ((uint4*)(g_vall + dst))[tid] = vv;
}

// ---------------- fused flash attention (HMMA) ----------------
// block = (qtile 64, head, win), 4 warps. O = softmax(Q K^T + bias) V
#define LDSH 136
__global__ __launch_bounds__(128)
void fused_attn_kernel()
{
    __shared__ __half smK[64][LDSH];
    __shared__ __half smV[64][LDSH];

    const int qt = blockIdx.x, head = blockIdx.y, win = blockIdx.z;
    const int wh = win / 12, ww = win % 12;
    const int tid = threadIdx.x, lane = tid & 31, w = tid >> 5;

    // ---- load Q tile into smK, then Q fragments into registers ----
    #pragma unroll
    for (int it = 0; it < 8; it++) {
        int idx = tid + it * 128;
        int r = idx >> 4, c16 = idx & 15;
        int qi = qt * 64 + r;
        uint4 v = make_uint4(0,0,0,0);
        if (qi < WA) {
            int t = qi / 45, l = qi % 45, rr = l / 9, cc2 = l % 9;
            int row = (t * HH + wh * 5 + rr) * WWID + ww * 9 + cc2;
            v = ((const uint4*)(hq + (size_t)row * 512 + head * 128))[c16];
        }
        *(uint4*)&smK[r][c16 * 8] = v;
    }
    __syncthreads();
    uint32_t qf[8][4];
    #pragma unroll
    for (int kk = 0; kk < 8; kk++) {
        uint32_t ad = smem_u32(&smK[w * 16 + (lane & 15)][kk * 16 + ((lane >> 4) << 3)]);
        LDSM4(qf[kk][0], qf[kk][1], qf[kk][2], qf[kk][3], ad);
    }
    __syncthreads();

    float o[16][4];
    #pragma unroll
    for (int i = 0; i < 16; i++)
        #pragma unroll
        for (int j = 0; j < 4; j++) o[i][j] = 0.f;
    float mrow0 = -1e30f, mrow1 = -1e30f;
    float lrow0 = 0.f, lrow1 = 0.f;
    const float* btab = g_bias + win * NKEY2;

    for (int c0 = 0; c0 < NKEY2; c0 += 64) {
        // ---- load K/V chunk ----
        const __half* kb = g_kall + ((size_t)win * NKEY2 + c0) * 512 + head * 128;
        const __half* vb = g_vall + ((size_t)win * NKEY2 + c0) * 512 + head * 128;
        #pragma unroll
        for (int it = 0; it < 8; it++) {
            int idx = tid + it * 128;
            int r = idx >> 4, c16 = idx & 15;
            *(uint4*)&smK[r][c16 * 8] = ((const uint4*)(kb + (size_t)r * 512))[c16];
            *(uint4*)&smV[r][c16 * 8] = ((const uint4*)(vb + (size_t)r * 512))[c16];
        }
        __syncthreads();

        // ---- S = Q K^T (16 rows x 64 keys per warp) ----
        float s[8][4];
        #pragma unroll
        for (int i = 0; i < 8; i++)
            #pragma unroll
            for (int j = 0; j < 4; j++) s[i][j] = 0.f;
        #pragma unroll
        for (int kg = 0; kg < 4; kg++) {
            #pragma unroll
            for (int kk = 0; kk < 8; kk++) {
                uint32_t r0, r1, r2, r3;
                uint32_t ad = smem_u32(&smK[kg * 16 + (lane & 15)][kk * 16 + ((lane >> 4) << 3)]);
                LDSM4(r0, r1, r2, r3, ad);
                MMA16816(s[kg * 2],     qf[kk], r0, r2);
                MMA16816(s[kg * 2 + 1], qf[kk], r1, r3);
            }
        }

        // ---- bias + row max ----
        float mx0 = -1e30f, mx1 = -1e30f;
        #pragma unroll
        for (int j = 0; j < 8; j++) {
            int n = c0 + j * 8 + (lane & 3) * 2;
            float b0 = btab[n], b1 = btab[n + 1];
            s[j][0] += b0; s[j][1] += b1; s[j][2] += b0; s[j][3] += b1;
            mx0 = fmaxf(mx0, fmaxf(s[j][0], s[j][1]));
            mx1 = fmaxf(mx1, fmaxf(s[j][2], s[j][3]));
        }
        mx0 = fmaxf(mx0, __shfl_xor_sync(0xffffffffu, mx0, 1));
        mx0 = fmaxf(mx0, __shfl_xor_sync(0xffffffffu, mx0, 2));
        mx1 = fmaxf(mx1, __shfl_xor_sync(0xffffffffu, mx1, 1));
        mx1 = fmaxf(mx1, __shfl_xor_sync(0xffffffffu, mx1, 2));

        float mn0 = fmaxf(mrow0, mx0), mn1 = fmaxf(mrow1, mx1);
        float al0 = __expf(mrow0 - mn0), al1 = __expf(mrow1 - mn1);
        lrow0 *= al0; lrow1 *= al1;
        mrow0 = mn0; mrow1 = mn1;
        #pragma unroll
        for (int i = 0; i < 16; i++) {
            o[i][0] *= al0; o[i][1] *= al0;
            o[i][2] *= al1; o[i][3] *= al1;
        }

        // ---- P = exp(S - m), pack A fragments ----
        uint32_t pa[4][4];
        float ls0 = 0.f, ls1 = 0.f;
        #pragma unroll
        for (int j = 0; j < 8; j++) {
            float p0 = __expf(s[j][0] - mn0);
            float p1 = __expf(s[j][1] - mn0);
            float p2 = __expf(s[j][2] - mn1);
            float p3 = __expf(s[j][3] - mn1);
            ls0 += p0 + p1; ls1 += p2 + p3;
            uint32_t u01 = h2u(__floats2half2_rn(p0, p1));
            uint32_t u23 = h2u(__floats2half2_rn(p2, p3));
            int kk2 = j >> 1;
            if ((j & 1) == 0) { pa[kk2][0] = u01; pa[kk2][1] = u23; }
            else              { pa[kk2][2] = u01; pa[kk2][3] = u23; }
        }
        lrow0 += ls0; lrow1 += ls1;

        // ---- O += P V ----
        #pragma unroll
        for (int kk2 = 0; kk2 < 4; kk2++) {
            #pragma unroll
            for (int nn = 0; nn < 8; nn++) {
                uint32_t r0, r1, r2, r3;
                uint32_t ad = smem_u32(&smV[kk2 * 16 + (lane & 15)][nn * 16 + ((lane >> 4) << 3)]);
                LDSM4T(r0, r1, r2, r3, ad);
                MMA16816(o[nn * 2],     pa[kk2], r0, r1);
                MMA16816(o[nn * 2 + 1], pa[kk2], r2, r3);
            }
        }
        __syncthreads();
    }

    // ---- FIX: reduce softmax denominator across the quad lanes that share
    // each C-fragment row (alphas were lane-uniform, so sum distributes) ----
    lrow0 += __shfl_xor_sync(0xffffffffu, lrow0, 1);
    lrow0 += __shfl_xor_sync(0xffffffffu, lrow0, 2);
    lrow1 += __shfl_xor_sync(0xffffffffu, lrow1, 1);
    lrow1 += __shfl_xor_sync(0xffffffffu, lrow1, 2);

    // ---- epilogue ----
    float inv0 = 1.f / lrow0, inv1 = 1.f / lrow1;
    int m0 = qt * 64 + w * 16 + (lane >> 2);
    int m1 = m0 + 8;
    int cbase = head * 128 + (lane & 3) * 2;
    #pragma unroll
    for (int nn = 0; nn < 16; nn++) {
        int col = cbase + nn * 8;
        if (m0 < WA)
            *(uint32_t*)(g_attn + (size_t)(win * WA + m0) * 512 + col)
                = h2u(__floats2half2_rn(o[nn][0] * inv0, o[nn][1] * inv0));
        if (m1 < WA)
            *(uint32_t*)(g_attn + (size_t)(win * WA + m1) * 512 + col)
                = h2u(__floats2half2_rn(o[nn][2] * inv1, o[nn][3] * inv1));
    }
}

// ---------------- launch ----------------
extern "C" void kernel_launch(void* const* d_in, const int* in_sizes, int n_in,
                              void* d_out, int out_size)
{
    const float* x        = (const float*)d_in[0];
    const float* x_pooled = (const float*)d_in[1];
    const float* qkv_w    = (const float*)d_in[2];
    const float* qkv_b    = (const float*)d_in[3];
    const float* proj_w   = (const float*)d_in[4];
    const float* proj_b   = (const float*)d_in[5];
    float* out = (float*)d_out;

    init_valid_kernel<<<1, 1>>>();
    bias_table_kernel<<<dim3(17, NWIN), 64>>>();

    {
        __half* dhx; cudaGetSymbolAddress((void**)&dhx, hx);
        __half* dwq; cudaGetSymbolAddress((void**)&dwq, hwqkv);
        __half* dwp; cudaGetSymbolAddress((void**)&dwp, hwproj);
        f32_to_f16_kernel<<<(QS/4 + 255)/256, 256>>>(x, dhx, QS/4);
        f32_to_f16_kernel<<<(1536*512/4 + 255)/256, 256>>>(qkv_w, dwq, 1536*512/4);
        f32_to_f16_kernel<<<(512*512/4 + 255)/256, 256>>>(proj_w, dwp, 512*512/4);
        conv_pooled_kernel<<<PTOK, 128>>>(x_pooled);
    }

    mma_gemm<1><<<dim3(12, 254, 1), 256>>>(nullptr, qkv_b);
    mma_gemm<2><<<dim3(12, 6, 1),   256>>>(nullptr, qkv_b);

    gather_kv_kernel<<<dim3(NKEY2, NWIN), 64>>>();

    fused_attn_kernel<<<dim3(4, 4, NWIN), 128>>>();

    mma_gemm<0><<<dim3(4, 254, 1), 256>>>(out, proj_b);
}

// round 6
// speedup vs baseline: 24.6889x; 1.1712x over previous
#include <cuda_runtime.h>
#include <cuda_fp16.h>
#include <stdint.h>
#include <math.h>

// ---------------- problem constants ----------------
#define TT    5
#define HH    60
#define WWID  108
#define CDIM  512
#define NTOK  (TT*HH*WWID)          // 32400
#define QS    (NTOK*CDIM)
#define PTOK  720
#define NWIN  144
#define NKEY  1050
#define NKEY2 1088                  // padded keys (17 chunks of 64)
#define WA    225
#define SCALE 0.08838834764831845f

// ---------------- scratch ----------------
__device__ __align__(256) __half hx    [QS];
__device__ __align__(256) __half hxp   [PTOK*CDIM];
__device__ __align__(256) __half hwqkv [1536*512];
__device__ __align__(256) __half hwproj[512*512];
__device__ __align__(256) __half hq [QS];
__device__ __align__(256) __half hk [QS];
__device__ __align__(256) __half hv [QS];
__device__ __align__(256) __half hqp[PTOK*CDIM];
__device__ __align__(256) __half hkp[PTOK*CDIM];
__device__ __align__(256) __half hvp[PTOK*CDIM];
__device__ __align__(256) __half g_kall[(size_t)NWIN*NKEY2*CDIM];
__device__ __align__(256) __half g_vall[(size_t)NWIN*NKEY2*CDIM];
__device__ __align__(256) float  g_bias[NWIN*NKEY2];
__device__ __align__(256) __half g_attn[QS];
__device__ int g_valid_ind[120];

// ---------------- helpers ----------------
__device__ __forceinline__ uint32_t smem_u32(const void* p) {
    uint32_t a;
    asm("{ .reg .u64 t; cvta.to.shared.u64 t, %1; cvt.u32.u64 %0, t; }" : "=r"(a) : "l"(p));
    return a;
}
__device__ __forceinline__ uint32_t h2u(__half2 h) { return *reinterpret_cast<uint32_t*>(&h); }

#define LDSM4(r0,r1,r2,r3,addr) \
    asm volatile("ldmatrix.sync.aligned.m8n8.x4.shared.b16 {%0,%1,%2,%3}, [%4];" \
        : "=r"(r0),"=r"(r1),"=r"(r2),"=r"(r3) : "r"(addr))
#define LDSM4T(r0,r1,r2,r3,addr) \
    asm volatile("ldmatrix.sync.aligned.m8n8.x4.trans.shared.b16 {%0,%1,%2,%3}, [%4];" \
        : "=r"(r0),"=r"(r1),"=r"(r2),"=r"(r3) : "r"(addr))

#define MMA16816(d,a,b0,b1) \
    asm volatile("mma.sync.aligned.m16n8k16.row.col.f32.f16.f16.f32 " \
        "{%0,%1,%2,%3}, {%4,%5,%6,%7}, {%8,%9}, {%0,%1,%2,%3};" \
        : "+f"((d)[0]),"+f"((d)[1]),"+f"((d)[2]),"+f"((d)[3]) \
        : "r"((a)[0]),"r"((a)[1]),"r"((a)[2]),"r"((a)[3]),"r"(b0),"r"(b1))

#define CPA16(dst, src, nbytes) \
    asm volatile("cp.async.cg.shared.global [%0], [%1], 16, %2;" \
        :: "r"(dst), "l"(src), "r"(nbytes))
#define CPA_COMMIT() asm volatile("cp.async.commit_group;" ::: "memory")
#define CPA_WAIT1()  asm volatile("cp.async.wait_group 1;" ::: "memory")

// ---------------- VALID_IND ----------------
__global__ void init_valid_kernel() {
    int cnt = 0;
    for (int idx = 0; idx < 180; idx++) {
        int si = idx / 45, l = idx % 45, r = l / 9, c = l % 9;
        bool valid;
        if      (si == 0) valid = (r >= 3) || (c >= 5);
        else if (si == 1) valid = (r >= 3) || (c <  4);
        else if (si == 2) valid = (r <  2) || (c >= 5);
        else              valid = (r <  2) || (c <  4);
        if (valid) g_valid_ind[cnt++] = idx;
    }
}

// ---------------- bias table ----------------
__global__ void bias_table_kernel() {
    int n = blockIdx.x * 64 + threadIdx.x;
    int win = blockIdx.y;
    if (n >= NKEY2) return;
    float b = 0.f;
    if (n >= NKEY) b = -1e30f;
    else if (n >= 825) {
        int p2 = (n - 825) % 45;
        int fr = p2 / 9, fc = p2 % 9;
        int gh = win / 12 + fr - 2, gw = win % 12 + fc - 4;
        if (gh < 0 || gh >= 12 || gw < 0 || gw >= 12) b = -100.f;
    }
    g_bias[win * NKEY2 + n] = b;
}

// ---------------- conversions ----------------
__global__ void f32_to_f16_kernel(const float* __restrict__ s, __half* __restrict__ d, int n4) {
    int i = blockIdx.x * blockDim.x + threadIdx.x;
    if (i < n4) {
        float4 f = ((const float4*)s)[i];
        ((uint2*)d)[i] = make_uint2(h2u(__floats2half2_rn(f.x, f.y)),
                                    h2u(__floats2half2_rn(f.z, f.w)));
    }
}
__global__ void conv_pooled_kernel(const float* __restrict__ xp) {
    int m = blockIdx.x;
    int sr = (m % 144) * 5 + m / 144;
    int tid = threadIdx.x;
    float4 f = ((const float4*)(xp + (size_t)sr * 512))[tid];
    ((uint2*)(hxp + (size_t)m * 512))[tid] =
        make_uint2(h2u(__floats2half2_rn(f.x, f.y)), h2u(__floats2half2_rn(f.z, f.w)));
}

// ---------------- HMMA GEMM (cp.async double-buffered) ----------------
template<int MODE>
__global__ __launch_bounds__(256)
void mma_gemm(float* __restrict__ outF, const float* __restrict__ bias)
{
    __shared__ __half As[2][128][40];
    __shared__ __half Bs[2][128][40];

    const int tid = threadIdx.x;
    const __half* A; const __half* B;
    int M, N;
    if (MODE == 0) { A = g_attn; B = hwproj; M = NTOK; N = 512;  }
    if (MODE == 1) { A = hx;     B = hwqkv;  M = NTOK; N = 1536; }
    if (MODE == 2) { A = hxp;    B = hwqkv;  M = PTOK; N = 1536; }
    const int K = 512, lda = 512, ldb = 512;

    const int m0 = blockIdx.y * 128;
    const int n0 = blockIdx.x * 128;
    const int lane = tid & 31, wid = tid >> 5;
    const int wm = wid & 3, wn = wid >> 2;

    float acc[2][8][4];
    #pragma unroll
    for (int a = 0; a < 2; a++)
        #pragma unroll
        for (int b = 0; b < 8; b++)
            #pragma unroll
            for (int c = 0; c < 4; c++) acc[a][b][c] = 0.f;

    // async tile loader
    const int r_ld = tid >> 2, cq_ld = tid & 3;
    auto load_tile = [&](int st, int k0) {
        #pragma unroll
        for (int it = 0; it < 2; it++) {
            int r = r_ld + it * 64;
            int gc = k0 + cq_ld * 8;
            int gm = m0 + r, gn = n0 + r;
            uint32_t da = smem_u32(&As[st][r][cq_ld * 8]);
            uint32_t db = smem_u32(&Bs[st][r][cq_ld * 8]);
            CPA16(da, A + (size_t)gm * lda + gc, (gm < M) ? 16 : 0);
            CPA16(db, B + (size_t)gn * ldb + gc, (gn < N) ? 16 : 0);
        }
    };

    load_tile(0, 0);
    CPA_COMMIT();

    const int NCH = K / 32;   // 16
    for (int kc = 0; kc < NCH; kc++) {
        if (kc + 1 < NCH) load_tile((kc + 1) & 1, (kc + 1) * 32);
        CPA_COMMIT();
        CPA_WAIT1();
        __syncthreads();
        const int st = kc & 1;
        #pragma unroll
        for (int ks = 0; ks < 2; ks++) {
            uint32_t afr[2][4];
            #pragma unroll
            for (int mi = 0; mi < 2; mi++) {
                uint32_t ad = smem_u32(&As[st][wm*32 + mi*16 + (lane & 15)][ks*16 + ((lane >> 4) << 3)]);
                LDSM4(afr[mi][0], afr[mi][1], afr[mi][2], afr[mi][3], ad);
            }
            uint32_t bfr[8][2];
            #pragma unroll
            for (int nj = 0; nj < 4; nj++) {
                uint32_t bd = smem_u32(&Bs[st][wn*64 + nj*16 + (lane & 15)][ks*16 + ((lane >> 4) << 3)]);
                uint32_t r0, r1, r2, r3;
                LDSM4(r0, r1, r2, r3, bd);
                bfr[nj*2][0] = r0;  bfr[nj*2][1] = r2;
                bfr[nj*2+1][0] = r1; bfr[nj*2+1][1] = r3;
            }
            #pragma unroll
            for (int mi = 0; mi < 2; mi++)
                #pragma unroll
                for (int ni = 0; ni < 8; ni++)
                    MMA16816(acc[mi][ni], afr[mi], bfr[ni][0], bfr[ni][1]);
        }
        __syncthreads();
    }

    const int rr = lane >> 2, cc = (lane & 3) * 2;
    #pragma unroll
    for (int mi = 0; mi < 2; mi++) {
        #pragma unroll
        for (int ni = 0; ni < 8; ni++) {
            int col = n0 + wn * 64 + ni * 8 + cc;
            #pragma unroll
            for (int h = 0; h < 2; h++) {
                int row = m0 + wm * 32 + mi * 16 + rr + h * 8;
                if (row >= M) continue;
                float v0 = acc[mi][ni][h * 2 + 0];
                float v1 = acc[mi][ni][h * 2 + 1];
                if (MODE == 0) {
                    *(float2*)(outF + (size_t)row * 512 + col) =
                        make_float2(v0 + bias[col], v1 + bias[col + 1]);
                } else {
                    v0 += bias[col]; v1 += bias[col + 1];
                    int pl = col >> 9, c2 = col & 511;
                    if (pl == 0) { v0 *= SCALE; v1 *= SCALE; }
                    __half* base;
                    if (MODE == 1) base = (pl == 0) ? hq : (pl == 1) ? hk : hv;
                    else           base = (pl == 0) ? hqp : (pl == 1) ? hkp : hvp;
                    *(uint32_t*)(base + (size_t)row * 512 + c2) = h2u(__floats2half2_rn(v0, v1));
                }
            }
        }
    }
}

// ---------------- gather K_all / V_all ----------------
__global__ __launch_bounds__(64)
void gather_kv_kernel() {
    int n = blockIdx.x, win = blockIdx.y;
    int wh = win / 12, ww = win % 12;
    int tid = threadIdx.x;

    bool zero = false;
    bool pooled = false;
    int row = 0;

    if (n >= NKEY) {
        zero = true;
    } else if (n < WA) {
        int t = n / 45, l = n % 45, r = l / 9, c = l % 9;
        row = (t * HH + wh * 5 + r) * WWID + ww * 9 + c;
    } else if (n < 825) {
        int j2 = n - 225, t = j2 / 120, j = j2 % 120;
        int vi = g_valid_ind[j];
        int si = vi / 45, l = vi % 45, r = l / 9, c = l % 9;
        int dh = (si < 2) ? 2 : -2;
        int dw = ((si & 1) == 0) ? 4 : -4;
        int h = (wh * 5 + r + dh + HH) % HH;
        int w = (ww * 9 + c + dw + WWID) % WWID;
        row = (t * HH + h) * WWID + w;
    } else {
        int j2 = n - 825, t = j2 / 45, p = j2 % 45, fr = p / 9, fc = p % 9;
        int gh = wh + fr - 2, gw = ww + fc - 4;
        if (gh < 0 || gh >= 12 || gw < 0 || gw >= 12) zero = true;
        else { row = t * 144 + gh * 12 + gw; pooled = true; }
    }

    uint4 kv = make_uint4(0,0,0,0), vv = kv;
    if (!zero) {
        const __half* kp = pooled ? hkp : hk;
        const __half* vp = pooled ? hvp : hv;
        kv = ((const uint4*)(kp + (size_t)row * 512))[tid];
        vv = ((const uint4*)(vp + (size_t)row * 512))[tid];
    }
    size_t dst = ((size_t)win * NKEY2 + n) * 512;
    ((uint4*)(g_kall + dst))[tid] = kv;
    ((uint4*)(g_vall + dst))[tid] = vv;
}

// ---------------- fused flash attention (HMMA, cp.async double-buffered) ----------------
#define LDSH 136
#define KVSTRIDE (64 * LDSH)             // halves per K (or V) stage
#define ATTN_SMEM (4 * KVSTRIDE * 2)     // bytes: K[2] + V[2]
__global__ __launch_bounds__(128)
void fused_attn_kernel()
{
    extern __shared__ __half dynsm[];
    // layout: K stage0 | K stage1 | V stage0 | V stage1
    __half* smKp[2] = { dynsm,                dynsm + KVSTRIDE };
    __half* smVp[2] = { dynsm + 2*KVSTRIDE,   dynsm + 3*KVSTRIDE };

    const int qt = blockIdx.x, head = blockIdx.y, win = blockIdx.z;
    const int wh = win / 12, ww = win % 12;
    const int tid = threadIdx.x, lane = tid & 31, w = tid >> 5;

    // ---- stage Q tile in K-stage0 smem, extract fragments ----
    #pragma unroll
    for (int it = 0; it < 8; it++) {
        int idx = tid + it * 128;
        int r = idx >> 4, c16 = idx & 15;
        int qi = qt * 64 + r;
        uint4 v = make_uint4(0,0,0,0);
        if (qi < WA) {
            int t = qi / 45, l = qi % 45, rr = l / 9, cc2 = l % 9;
            int row = (t * HH + wh * 5 + rr) * WWID + ww * 9 + cc2;
            v = ((const uint4*)(hq + (size_t)row * 512 + head * 128))[c16];
        }
        *(uint4*)&smKp[0][r * LDSH + c16 * 8] = v;
    }
    __syncthreads();
    uint32_t qf[8][4];
    #pragma unroll
    for (int kk = 0; kk < 8; kk++) {
        uint32_t ad = smem_u32(&smKp[0][(w * 16 + (lane & 15)) * LDSH + kk * 16 + ((lane >> 4) << 3)]);
        LDSM4(qf[kk][0], qf[kk][1], qf[kk][2], qf[kk][3], ad);
    }
    __syncthreads();

    float o[16][4];
    #pragma unroll
    for (int i = 0; i < 16; i++)
        #pragma unroll
        for (int j = 0; j < 4; j++) o[i][j] = 0.f;
    float mrow0 = -1e30f, mrow1 = -1e30f;
    float lrow0 = 0.f, lrow1 = 0.f;
    const float* btab = g_bias + win * NKEY2;

    const __half* kbase = g_kall + (size_t)win * NKEY2 * 512 + head * 128;
    const __half* vbase = g_vall + (size_t)win * NKEY2 * 512 + head * 128;
    const int r_ld = tid >> 4, c16_ld = tid & 15;

    auto load_chunk = [&](int st, int c0) {
        #pragma unroll
        for (int it = 0; it < 8; it++) {
            int r = r_ld + it * 8;
            uint32_t dk = smem_u32(&smKp[st][r * LDSH + c16_ld * 8]);
            uint32_t dv = smem_u32(&smVp[st][r * LDSH + c16_ld * 8]);
            const __half* sk = kbase + (size_t)(c0 + r) * 512 + c16_ld * 8;
            const __half* sv = vbase + (size_t)(c0 + r) * 512 + c16_ld * 8;
            CPA16(dk, sk, 16);
            CPA16(dv, sv, 16);
        }
    };

    load_chunk(0, 0);
    CPA_COMMIT();

    const int NCH = NKEY2 / 64;   // 17
    for (int c = 0; c < NCH; c++) {
        if (c + 1 < NCH) load_chunk((c + 1) & 1, (c + 1) * 64);
        CPA_COMMIT();
        CPA_WAIT1();
        __syncthreads();
        const int st = c & 1;
        const int c0 = c * 64;
        const __half* smK = smKp[st];
        const __half* smV = smVp[st];

        // ---- S = Q K^T ----
        float s[8][4];
        #pragma unroll
        for (int i = 0; i < 8; i++)
            #pragma unroll
            for (int j = 0; j < 4; j++) s[i][j] = 0.f;
        #pragma unroll
        for (int kg = 0; kg < 4; kg++) {
            #pragma unroll
            for (int kk = 0; kk < 8; kk++) {
                uint32_t r0, r1, r2, r3;
                uint32_t ad = smem_u32(&smK[(kg * 16 + (lane & 15)) * LDSH + kk * 16 + ((lane >> 4) << 3)]);
                LDSM4(r0, r1, r2, r3, ad);
                MMA16816(s[kg * 2],     qf[kk], r0, r2);
                MMA16816(s[kg * 2 + 1], qf[kk], r1, r3);
            }
        }

        // ---- bias + row max ----
        float mx0 = -1e30f, mx1 = -1e30f;
        #pragma unroll
        for (int j = 0; j < 8; j++) {
            int n = c0 + j * 8 + (lane & 3) * 2;
            float b0 = btab[n], b1 = btab[n + 1];
            s[j][0] += b0; s[j][1] += b1; s[j][2] += b0; s[j][3] += b1;
            mx0 = fmaxf(mx0, fmaxf(s[j][0], s[j][1]));
            mx1 = fmaxf(mx1, fmaxf(s[j][2], s[j][3]));
        }
        mx0 = fmaxf(mx0, __shfl_xor_sync(0xffffffffu, mx0, 1));
        mx0 = fmaxf(mx0, __shfl_xor_sync(0xffffffffu, mx0, 2));
        mx1 = fmaxf(mx1, __shfl_xor_sync(0xffffffffu, mx1, 1));
        mx1 = fmaxf(mx1, __shfl_xor_sync(0xffffffffu, mx1, 2));

        float mn0 = fmaxf(mrow0, mx0), mn1 = fmaxf(mrow1, mx1);
        float al0 = __expf(mrow0 - mn0), al1 = __expf(mrow1 - mn1);
        lrow0 *= al0; lrow1 *= al1;
        mrow0 = mn0; mrow1 = mn1;
        #pragma unroll
        for (int i = 0; i < 16; i++) {
            o[i][0] *= al0; o[i][1] *= al0;
            o[i][2] *= al1; o[i][3] *= al1;
        }

        // ---- P = exp(S - m), pack A fragments ----
        uint32_t pa[4][4];
        float ls0 = 0.f, ls1 = 0.f;
        #pragma unroll
        for (int j = 0; j < 8; j++) {
            float p0 = __expf(s[j][0] - mn0);
            float p1 = __expf(s[j][1] - mn0);
            float p2 = __expf(s[j][2] - mn1);
            float p3 = __expf(s[j][3] - mn1);
            ls0 += p0 + p1; ls1 += p2 + p3;
            uint32_t u01 = h2u(__floats2half2_rn(p0, p1));
            uint32_t u23 = h2u(__floats2half2_rn(p2, p3));
            int kk2 = j >> 1;
            if ((j & 1) == 0) { pa[kk2][0] = u01; pa[kk2][1] = u23; }
            else              { pa[kk2][2] = u01; pa[kk2][3] = u23; }
        }
        lrow0 += ls0; lrow1 += ls1;

        // ---- O += P V ----
        #pragma unroll
        for (int kk2 = 0; kk2 < 4; kk2++) {
            #pragma unroll
            for (int nn = 0; nn < 8; nn++) {
                uint32_t r0, r1, r2, r3;
                uint32_t ad = smem_u32(&smV[(kk2 * 16 + (lane & 15)) * LDSH + nn * 16 + ((lane >> 4) << 3)]);
                LDSM4T(r0, r1, r2, r3, ad);
                MMA16816(o[nn * 2],     pa[kk2], r0, r1);
                MMA16816(o[nn * 2 + 1], pa[kk2], r2, r3);
            }
        }
        __syncthreads();
    }

    // ---- reduce softmax denominator across quad lanes ----
    lrow0 += __shfl_xor_sync(0xffffffffu, lrow0, 1);
    lrow0 += __shfl_xor_sync(0xffffffffu, lrow0, 2);
    lrow1 += __shfl_xor_sync(0xffffffffu, lrow1, 1);
    lrow1 += __shfl_xor_sync(0xffffffffu, lrow1, 2);

    // ---- epilogue ----
    float inv0 = 1.f / lrow0, inv1 = 1.f / lrow1;
    int m0 = qt * 64 + w * 16 + (lane >> 2);
    int m1 = m0 + 8;
    int cbase = head * 128 + (lane & 3) * 2;
    #pragma unroll
    for (int nn = 0; nn < 16; nn++) {
        int col = cbase + nn * 8;
        if (m0 < WA)
            *(uint32_t*)(g_attn + (size_t)(win * WA + m0) * 512 + col)
                = h2u(__floats2half2_rn(o[nn][0] * inv0, o[nn][1] * inv0));
        if (m1 < WA)
            *(uint32_t*)(g_attn + (size_t)(win * WA + m1) * 512 + col)
                = h2u(__floats2half2_rn(o[nn][2] * inv1, o[nn][3] * inv1));
    }
}

// ---------------- launch ----------------
extern "C" void kernel_launch(void* const* d_in, const int* in_sizes, int n_in,
                              void* d_out, int out_size)
{
    const float* x        = (const float*)d_in[0];
    const float* x_pooled = (const float*)d_in[1];
    const float* qkv_w    = (const float*)d_in[2];
    const float* qkv_b    = (const float*)d_in[3];
    const float* proj_w   = (const float*)d_in[4];
    const float* proj_b   = (const float*)d_in[5];
    float* out = (float*)d_out;

    static bool attr_set = false;
    if (!attr_set) {
        cudaFuncSetAttribute(fused_attn_kernel,
                             cudaFuncAttributeMaxDynamicSharedMemorySize, ATTN_SMEM);
        attr_set = true;
    }

    init_valid_kernel<<<1, 1>>>();
    bias_table_kernel<<<dim3(17, NWIN), 64>>>();

    {
        __half* dhx; cudaGetSymbolAddress((void**)&dhx, hx);
        __half* dwq; cudaGetSymbolAddress((void**)&dwq, hwqkv);
        __half* dwp; cudaGetSymbolAddress((void**)&dwp, hwproj);
        f32_to_f16_kernel<<<(QS/4 + 255)/256, 256>>>(x, dhx, QS/4);
        f32_to_f16_kernel<<<(1536*512/4 + 255)/256, 256>>>(qkv_w, dwq, 1536*512/4);
        f32_to_f16_kernel<<<(512*512/4 + 255)/256, 256>>>(proj_w, dwp, 512*512/4);
        conv_pooled_kernel<<<PTOK, 128>>>(x_pooled);
    }

    mma_gemm<1><<<dim3(12, 254, 1), 256>>>(nullptr, qkv_b);
    mma_gemm<2><<<dim3(12, 6, 1),   256>>>(nullptr, qkv_b);

    gather_kv_kernel<<<dim3(NKEY2, NWIN), 64>>>();

    fused_attn_kernel<<<dim3(4, 4, NWIN), 128, ATTN_SMEM>>>();

    mma_gemm<0><<<dim3(4, 254, 1), 256>>>(out, proj_b);
}

// round 7
// speedup vs baseline: 29.2366x; 1.1842x over previous
#include <cuda_runtime.h>
#include <cuda_fp16.h>
#include <stdint.h>
#include <math.h>

// ---------------- problem constants ----------------
#define TT    5
#define HH    60
#define WWID  108
#define CDIM  512
#define NTOK  (TT*HH*WWID)          // 32400
#define QS    (NTOK*CDIM)
#define PTOK  720
#define XTOK  (NTOK+PTOK)           // unified token count (x + pooled)
#define NWIN  144
#define NKEY  1050
#define NKEY2 1088                  // padded keys (17 chunks of 64)
#define WA    225
#define SCALE 0.08838834764831845f

// ---------------- scratch ----------------
__device__ __align__(256) __half hx    [QS];
__device__ __align__(256) __half hxp   [PTOK*CDIM];
__device__ __align__(256) __half hwqkv [1536*512];
__device__ __align__(256) __half hwproj[512*512];
__device__ __align__(256) __half hq [(size_t)XTOK*CDIM];
__device__ __align__(256) __half hk [(size_t)XTOK*CDIM];
__device__ __align__(256) __half hv [(size_t)XTOK*CDIM];
__device__ __align__(256) float  g_bias[NWIN*NKEY2];
__device__ __align__(256) int    g_kidx[NWIN*NKEY2];
__device__ __align__(256) __half g_attn[QS];
__device__ int g_valid_ind[120];

// ---------------- helpers ----------------
__device__ __forceinline__ uint32_t smem_u32(const void* p) {
    uint32_t a;
    asm("{ .reg .u64 t; cvta.to.shared.u64 t, %1; cvt.u32.u64 %0, t; }" : "=r"(a) : "l"(p));
    return a;
}
__device__ __forceinline__ uint32_t h2u(__half2 h) { return *reinterpret_cast<uint32_t*>(&h); }

#define LDSM4(r0,r1,r2,r3,addr) \
    asm volatile("ldmatrix.sync.aligned.m8n8.x4.shared.b16 {%0,%1,%2,%3}, [%4];" \
        : "=r"(r0),"=r"(r1),"=r"(r2),"=r"(r3) : "r"(addr))
#define LDSM4T(r0,r1,r2,r3,addr) \
    asm volatile("ldmatrix.sync.aligned.m8n8.x4.trans.shared.b16 {%0,%1,%2,%3}, [%4];" \
        : "=r"(r0),"=r"(r1),"=r"(r2),"=r"(r3) : "r"(addr))

#define MMA16816(d,a,b0,b1) \
    asm volatile("mma.sync.aligned.m16n8k16.row.col.f32.f16.f16.f32 " \
        "{%0,%1,%2,%3}, {%4,%5,%6,%7}, {%8,%9}, {%0,%1,%2,%3};" \
        : "+f"((d)[0]),"+f"((d)[1]),"+f"((d)[2]),"+f"((d)[3]) \
        : "r"((a)[0]),"r"((a)[1]),"r"((a)[2]),"r"((a)[3]),"r"(b0),"r"(b1))

#define CPA16(dst, src, nbytes) \
    asm volatile("cp.async.cg.shared.global [%0], [%1], 16, %2;" \
        :: "r"(dst), "l"(src), "r"(nbytes))
#define CPA_COMMIT() asm volatile("cp.async.commit_group;" ::: "memory")
#define CPA_WAIT1()  asm volatile("cp.async.wait_group 1;" ::: "memory")

// ---------------- VALID_IND ----------------
__global__ void init_valid_kernel() {
    int cnt = 0;
    for (int idx = 0; idx < 180; idx++) {
        int si = idx / 45, l = idx % 45, r = l / 9, c = l % 9;
        bool valid;
        if      (si == 0) valid = (r >= 3) || (c >= 5);
        else if (si == 1) valid = (r >= 3) || (c <  4);
        else if (si == 2) valid = (r <  2) || (c >= 5);
        else              valid = (r <  2) || (c <  4);
        if (valid) g_valid_ind[cnt++] = idx;
    }
}

// ---------------- bias + key-index tables ----------------
__global__ void bias_table_kernel() {
    int n = blockIdx.x * 64 + threadIdx.x;
    int win = blockIdx.y;
    if (n >= NKEY2) return;
    float b = 0.f;
    if (n >= NKEY) b = -1e30f;
    else if (n >= 825) {
        int p2 = (n - 825) % 45;
        int fr = p2 / 9, fc = p2 % 9;
        int gh = win / 12 + fr - 2, gw = win % 12 + fc - 4;
        if (gh < 0 || gh >= 12 || gw < 0 || gw >= 12) b = -100.f;
    }
    g_bias[win * NKEY2 + n] = b;
}

__global__ void build_kidx_kernel() {
    int n = blockIdx.x * 64 + threadIdx.x;
    int win = blockIdx.y;
    if (n >= NKEY2) return;
    int wh = win / 12, ww = win % 12;
    int e = -1;
    if (n < WA) {
        int t = n / 45, l = n % 45, r = l / 9, c = l % 9;
        e = (t * HH + wh * 5 + r) * WWID + ww * 9 + c;
    } else if (n < 825) {
        int j2 = n - 225, t = j2 / 120, j = j2 % 120;
        int vi = g_valid_ind[j];
        int si = vi / 45, l = vi % 45, r = l / 9, c = l % 9;
        int dh = (si < 2) ? 2 : -2;
        int dw = ((si & 1) == 0) ? 4 : -4;
        int h = (wh * 5 + r + dh + HH) % HH;
        int w = (ww * 9 + c + dw + WWID) % WWID;
        e = (t * HH + h) * WWID + w;
    } else if (n < NKEY) {
        int j2 = n - 825, t = j2 / 45, p = j2 % 45, fr = p / 9, fc = p % 9;
        int gh = wh + fr - 2, gw = ww + fc - 4;
        if (gh >= 0 && gh < 12 && gw >= 0 && gw < 12)
            e = NTOK + t * 144 + gh * 12 + gw;
    }
    g_kidx[win * NKEY2 + n] = e;
}

// ---------------- conversions ----------------
__global__ void f32_to_f16_kernel(const float* __restrict__ s, __half* __restrict__ d, int n4) {
    int i = blockIdx.x * blockDim.x + threadIdx.x;
    if (i < n4) {
        float4 f = ((const float4*)s)[i];
        ((uint2*)d)[i] = make_uint2(h2u(__floats2half2_rn(f.x, f.y)),
                                    h2u(__floats2half2_rn(f.z, f.w)));
    }
}
__global__ void conv_pooled_kernel(const float* __restrict__ xp) {
    int m = blockIdx.x;
    int sr = (m % 144) * 5 + m / 144;
    int tid = threadIdx.x;
    float4 f = ((const float4*)(xp + (size_t)sr * 512))[tid];
    ((uint2*)(hxp + (size_t)m * 512))[tid] =
        make_uint2(h2u(__floats2half2_rn(f.x, f.y)), h2u(__floats2half2_rn(f.z, f.w)));
}

// ---------------- HMMA GEMM (cp.async double-buffered) ----------------
// MODE 0: proj   A=g_attn B=hwproj M=32400 N=512  -> outF(+bias)
// MODE 1: qkv    A=hx     B=hwqkv  M=32400 N=1536 -> hq(*SCALE)/hk/hv rows [0,NTOK)
// MODE 2: qkv-p  A=hxp    B=hwqkv  M=720   N=1536 -> hq/hk/hv rows [NTOK,XTOK)
template<int MODE>
__global__ __launch_bounds__(256)
void mma_gemm(float* __restrict__ outF, const float* __restrict__ bias)
{
    __shared__ __half As[2][128][40];
    __shared__ __half Bs[2][128][40];

    const int tid = threadIdx.x;
    const __half* A; const __half* B;
    int M, N;
    if (MODE == 0) { A = g_attn; B = hwproj; M = NTOK; N = 512;  }
    if (MODE == 1) { A = hx;     B = hwqkv;  M = NTOK; N = 1536; }
    if (MODE == 2) { A = hxp;    B = hwqkv;  M = PTOK; N = 1536; }
    const int K = 512, lda = 512, ldb = 512;

    const int m0 = blockIdx.y * 128;
    const int n0 = blockIdx.x * 128;
    const int lane = tid & 31, wid = tid >> 5;
    const int wm = wid & 3, wn = wid >> 2;

    float acc[2][8][4];
    #pragma unroll
    for (int a = 0; a < 2; a++)
        #pragma unroll
        for (int b = 0; b < 8; b++)
            #pragma unroll
            for (int c = 0; c < 4; c++) acc[a][b][c] = 0.f;

    const int r_ld = tid >> 2, cq_ld = tid & 3;
    auto load_tile = [&](int st, int k0) {
        #pragma unroll
        for (int it = 0; it < 2; it++) {
            int r = r_ld + it * 64;
            int gc = k0 + cq_ld * 8;
            int gm = m0 + r, gn = n0 + r;
            uint32_t da = smem_u32(&As[st][r][cq_ld * 8]);
            uint32_t db = smem_u32(&Bs[st][r][cq_ld * 8]);
            CPA16(da, A + (size_t)gm * lda + gc, (gm < M) ? 16 : 0);
            CPA16(db, B + (size_t)gn * ldb + gc, (gn < N) ? 16 : 0);
        }
    };

    load_tile(0, 0);
    CPA_COMMIT();

    const int NCH = K / 32;
    for (int kc = 0; kc < NCH; kc++) {
        if (kc + 1 < NCH) load_tile((kc + 1) & 1, (kc + 1) * 32);
        CPA_COMMIT();
        CPA_WAIT1();
        __syncthreads();
        const int st = kc & 1;
        #pragma unroll
        for (int ks = 0; ks < 2; ks++) {
            uint32_t afr[2][4];
            #pragma unroll
            for (int mi = 0; mi < 2; mi++) {
                uint32_t ad = smem_u32(&As[st][wm*32 + mi*16 + (lane & 15)][ks*16 + ((lane >> 4) << 3)]);
                LDSM4(afr[mi][0], afr[mi][1], afr[mi][2], afr[mi][3], ad);
            }
            uint32_t bfr[8][2];
            #pragma unroll
            for (int nj = 0; nj < 4; nj++) {
                uint32_t bd = smem_u32(&Bs[st][wn*64 + nj*16 + (lane & 15)][ks*16 + ((lane >> 4) << 3)]);
                uint32_t r0, r1, r2, r3;
                LDSM4(r0, r1, r2, r3, bd);
                bfr[nj*2][0] = r0;  bfr[nj*2][1] = r2;
                bfr[nj*2+1][0] = r1; bfr[nj*2+1][1] = r3;
            }
            #pragma unroll
            for (int mi = 0; mi < 2; mi++)
                #pragma unroll
                for (int ni = 0; ni < 8; ni++)
                    MMA16816(acc[mi][ni], afr[mi], bfr[ni][0], bfr[ni][1]);
        }
        __syncthreads();
    }

    const int rr = lane >> 2, cc = (lane & 3) * 2;
    #pragma unroll
    for (int mi = 0; mi < 2; mi++) {
        #pragma unroll
        for (int ni = 0; ni < 8; ni++) {
            int col = n0 + wn * 64 + ni * 8 + cc;
            #pragma unroll
            for (int h = 0; h < 2; h++) {
                int row = m0 + wm * 32 + mi * 16 + rr + h * 8;
                if (row >= M) continue;
                float v0 = acc[mi][ni][h * 2 + 0];
                float v1 = acc[mi][ni][h * 2 + 1];
                if (MODE == 0) {
                    *(float2*)(outF + (size_t)row * 512 + col) =
                        make_float2(v0 + bias[col], v1 + bias[col + 1]);
                } else {
                    v0 += bias[col]; v1 += bias[col + 1];
                    int pl = col >> 9, c2 = col & 511;
                    if (pl == 0) { v0 *= SCALE; v1 *= SCALE; }
                    __half* base = (pl == 0) ? hq : (pl == 1) ? hk : hv;
                    size_t grow = (MODE == 1) ? row : (NTOK + row);
                    *(uint32_t*)(base + grow * 512 + c2) = h2u(__floats2half2_rn(v0, v1));
                }
            }
        }
    }
}

// ---------------- fused flash attention (HMMA, cp.async, direct gather) ----------------
#define LDSH 136
#define KVSTRIDE (64 * LDSH)
#define ATTN_SMEM (4 * KVSTRIDE * 2)
__global__ __launch_bounds__(128)
void fused_attn_kernel()
{
    extern __shared__ __half dynsm[];
    __half* smKp[2] = { dynsm,                dynsm + KVSTRIDE };
    __half* smVp[2] = { dynsm + 2*KVSTRIDE,   dynsm + 3*KVSTRIDE };

    const int qt = blockIdx.x, head = blockIdx.y, win = blockIdx.z;
    const int wh = win / 12, ww = win % 12;
    const int tid = threadIdx.x, lane = tid & 31, w = tid >> 5;

    // ---- stage Q tile, extract fragments ----
    #pragma unroll
    for (int it = 0; it < 8; it++) {
        int idx = tid + it * 128;
        int r = idx >> 4, c16 = idx & 15;
        int qi = qt * 64 + r;
        uint4 v = make_uint4(0,0,0,0);
        if (qi < WA) {
            int t = qi / 45, l = qi % 45, rr = l / 9, cc2 = l % 9;
            int row = (t * HH + wh * 5 + rr) * WWID + ww * 9 + cc2;
            v = ((const uint4*)(hq + (size_t)row * 512 + head * 128))[c16];
        }
        *(uint4*)&smKp[0][r * LDSH + c16 * 8] = v;
    }
    __syncthreads();
    uint32_t qf[8][4];
    #pragma unroll
    for (int kk = 0; kk < 8; kk++) {
        uint32_t ad = smem_u32(&smKp[0][(w * 16 + (lane & 15)) * LDSH + kk * 16 + ((lane >> 4) << 3)]);
        LDSM4(qf[kk][0], qf[kk][1], qf[kk][2], qf[kk][3], ad);
    }
    __syncthreads();

    float o[16][4];
    #pragma unroll
    for (int i = 0; i < 16; i++)
        #pragma unroll
        for (int j = 0; j < 4; j++) o[i][j] = 0.f;
    float mrow0 = -1e30f, mrow1 = -1e30f;
    float lrow0 = 0.f, lrow1 = 0.f;
    const float* btab = g_bias + win * NKEY2;
    const int* kidxw = g_kidx + win * NKEY2;

    const int r_ld = tid >> 4, c16_ld = tid & 15;
    const size_t hoff = (size_t)head * 128 + c16_ld * 8;

    auto load_chunk = [&](int st, int c0) {
        #pragma unroll
        for (int it = 0; it < 8; it++) {
            int r = r_ld + it * 8;
            int e = kidxw[c0 + r];
            int sz = (e < 0) ? 0 : 16;
            size_t off = (size_t)((e < 0) ? 0 : e) * 512 + hoff;
            uint32_t dk = smem_u32(&smKp[st][r * LDSH + c16_ld * 8]);
            uint32_t dv = smem_u32(&smVp[st][r * LDSH + c16_ld * 8]);
            CPA16(dk, hk + off, sz);
            CPA16(dv, hv + off, sz);
        }
    };

    load_chunk(0, 0);
    CPA_COMMIT();

    const int NCH = NKEY2 / 64;   // 17
    for (int c = 0; c < NCH; c++) {
        if (c + 1 < NCH) load_chunk((c + 1) & 1, (c + 1) * 64);
        CPA_COMMIT();
        CPA_WAIT1();
        __syncthreads();
        const int st = c & 1;
        const int c0 = c * 64;
        const __half* smK = smKp[st];
        const __half* smV = smVp[st];

        // ---- S = Q K^T ----
        float s[8][4];
        #pragma unroll
        for (int i = 0; i < 8; i++)
            #pragma unroll
            for (int j = 0; j < 4; j++) s[i][j] = 0.f;
        #pragma unroll
        for (int kg = 0; kg < 4; kg++) {
            #pragma unroll
            for (int kk = 0; kk < 8; kk++) {
                uint32_t r0, r1, r2, r3;
                uint32_t ad = smem_u32(&smK[(kg * 16 + (lane & 15)) * LDSH + kk * 16 + ((lane >> 4) << 3)]);
                LDSM4(r0, r1, r2, r3, ad);
                MMA16816(s[kg * 2],     qf[kk], r0, r2);
                MMA16816(s[kg * 2 + 1], qf[kk], r1, r3);
            }
        }

        // ---- bias + row max ----
        float mx0 = -1e30f, mx1 = -1e30f;
        #pragma unroll
        for (int j = 0; j < 8; j++) {
            int n = c0 + j * 8 + (lane & 3) * 2;
            float b0 = btab[n], b1 = btab[n + 1];
            s[j][0] += b0; s[j][1] += b1; s[j][2] += b0; s[j][3] += b1;
            mx0 = fmaxf(mx0, fmaxf(s[j][0], s[j][1]));
            mx1 = fmaxf(mx1, fmaxf(s[j][2], s[j][3]));
        }
        mx0 = fmaxf(mx0, __shfl_xor_sync(0xffffffffu, mx0, 1));
        mx0 = fmaxf(mx0, __shfl_xor_sync(0xffffffffu, mx0, 2));
        mx1 = fmaxf(mx1, __shfl_xor_sync(0xffffffffu, mx1, 1));
        mx1 = fmaxf(mx1, __shfl_xor_sync(0xffffffffu, mx1, 2));

        float mn0 = fmaxf(mrow0, mx0), mn1 = fmaxf(mrow1, mx1);
        float al0 = __expf(mrow0 - mn0), al1 = __expf(mrow1 - mn1);
        lrow0 *= al0; lrow1 *= al1;
        mrow0 = mn0; mrow1 = mn1;
        #pragma unroll
        for (int i = 0; i < 16; i++) {
            o[i][0] *= al0; o[i][1] *= al0;
            o[i][2] *= al1; o[i][3] *= al1;
        }

        // ---- P = exp(S - m), pack A fragments ----
        uint32_t pa[4][4];
        float ls0 = 0.f, ls1 = 0.f;
        #pragma unroll
        for (int j = 0; j < 8; j++) {
            float p0 = __expf(s[j][0] - mn0);
            float p1 = __expf(s[j][1] - mn0);
            float p2 = __expf(s[j][2] - mn1);
            float p3 = __expf(s[j][3] - mn1);
            ls0 += p0 + p1; ls1 += p2 + p3;
            uint32_t u01 = h2u(__floats2half2_rn(p0, p1));
            uint32_t u23 = h2u(__floats2half2_rn(p2, p3));
            int kk2 = j >> 1;
            if ((j & 1) == 0) { pa[kk2][0] = u01; pa[kk2][1] = u23; }
            else              { pa[kk2][2] = u01; pa[kk2][3] = u23; }
        }
        lrow0 += ls0; lrow1 += ls1;

        // ---- O += P V ----
        #pragma unroll
        for (int kk2 = 0; kk2 < 4; kk2++) {
            #pragma unroll
            for (int nn = 0; nn < 8; nn++) {
                uint32_t r0, r1, r2, r3;
                uint32_t ad = smem_u32(&smV[(kk2 * 16 + (lane & 15)) * LDSH + nn * 16 + ((lane >> 4) << 3)]);
                LDSM4T(r0, r1, r2, r3, ad);
                MMA16816(o[nn * 2],     pa[kk2], r0, r1);
                MMA16816(o[nn * 2 + 1], pa[kk2], r2, r3);
            }
        }
        __syncthreads();
    }

    // ---- reduce softmax denominator across quad lanes ----
    lrow0 += __shfl_xor_sync(0xffffffffu, lrow0, 1);
    lrow0 += __shfl_xor_sync(0xffffffffu, lrow0, 2);
    lrow1 += __shfl_xor_sync(0xffffffffu, lrow1, 1);
    lrow1 += __shfl_xor_sync(0xffffffffu, lrow1, 2);

    // ---- epilogue ----
    float inv0 = 1.f / lrow0, inv1 = 1.f / lrow1;
    int m0 = qt * 64 + w * 16 + (lane >> 2);
    int m1 = m0 + 8;
    int cbase = head * 128 + (lane & 3) * 2;
    #pragma unroll
    for (int nn = 0; nn < 16; nn++) {
        int col = cbase + nn * 8;
        if (m0 < WA)
            *(uint32_t*)(g_attn + (size_t)(win * WA + m0) * 512 + col)
                = h2u(__floats2half2_rn(o[nn][0] * inv0, o[nn][1] * inv0));
        if (m1 < WA)
            *(uint32_t*)(g_attn + (size_t)(win * WA + m1) * 512 + col)
                = h2u(__floats2half2_rn(o[nn][2] * inv1, o[nn][3] * inv1));
    }
}

// ---------------- launch ----------------
extern "C" void kernel_launch(void* const* d_in, const int* in_sizes, int n_in,
                              void* d_out, int out_size)
{
    const float* x        = (const float*)d_in[0];
    const float* x_pooled = (const float*)d_in[1];
    const float* qkv_w    = (const float*)d_in[2];
    const float* qkv_b    = (const float*)d_in[3];
    const float* proj_w   = (const float*)d_in[4];
    const float* proj_b   = (const float*)d_in[5];
    float* out = (float*)d_out;

    static bool attr_set = false;
    if (!attr_set) {
        cudaFuncSetAttribute(fused_attn_kernel,
                             cudaFuncAttributeMaxDynamicSharedMemorySize, ATTN_SMEM);
        attr_set = true;
    }

    init_valid_kernel<<<1, 1>>>();
    bias_table_kernel<<<dim3(17, NWIN), 64>>>();
    build_kidx_kernel<<<dim3(17, NWIN), 64>>>();

    {
        __half* dhx; cudaGetSymbolAddress((void**)&dhx, hx);
        __half* dwq; cudaGetSymbolAddress((void**)&dwq, hwqkv);
        __half* dwp; cudaGetSymbolAddress((void**)&dwp, hwproj);
        f32_to_f16_kernel<<<(QS/4 + 255)/256, 256>>>(x, dhx, QS/4);
        f32_to_f16_kernel<<<(1536*512/4 + 255)/256, 256>>>(qkv_w, dwq, 1536*512/4);
        f32_to_f16_kernel<<<(512*512/4 + 255)/256, 256>>>(proj_w, dwp, 512*512/4);
        conv_pooled_kernel<<<PTOK, 128>>>(x_pooled);
    }

    mma_gemm<1><<<dim3(12, 254, 1), 256>>>(nullptr, qkv_b);
    mma_gemm<2><<<dim3(12, 6, 1),   256>>>(nullptr, qkv_b);

    fused_attn_kernel<<<dim3(4, 4, NWIN), 128, ATTN_SMEM>>>();

    mma_gemm<0><<<dim3(4, 254, 1), 256>>>(out, proj_b);
}